// round 11
// baseline (speedup 1.0000x reference)
#include <cuda_runtime.h>
#include <math.h>

// ---------------- problem constants ----------------
constexpr int B_   = 2;
constexpr int N_   = 768;
constexpr int D_   = 512;
constexpr int H_   = 8;
constexpr int P_   = 64;
constexpr int C_   = 256;
constexpr int L_   = 6;
constexpr int NSEQ = 8;
constexpr int NSP  = 8;
constexpr int NRD  = 16;
constexpr int K_   = 2*NSEQ + NSP + NRD;  // 40
constexpr int DH_  = D_ / H_;             // 64
constexpr int BN_  = B_ * N_;             // 1536
constexpr int D3_  = 3 * D_;              // 1536
constexpr int D4_  = 4 * D_;              // 2048

// ---------------- device scratch (static: no allocations) ----------------
__device__ float g_x   [BN_ * D_];
__device__ float g_h   [BN_ * D_];
__device__ float g_xn  [BN_ * D_];
__device__ float g_qkv [BN_ * D3_];
__device__ float g_o   [BN_ * D_];
__device__ float g_t1  [BN_ * D4_];
__device__ float g_cond[L_ * BN_ * 2 * D_];
__device__ float g_bias[L_ * BN_ * H_ * K_];
__device__ float g_wqkv[L_ * D_ * D3_];
__device__ int   g_nidx[BN_ * K_];
__device__ int   g_nval[BN_ * K_];

// ---------------- helpers ----------------
__device__ __forceinline__ float gelu_f(float x) {
    // jax.nn.gelu approximate=True (default): tanh approximation
    float x3 = x * x * x;
    float t  = tanhf(0.7978845608028654f * (x + 0.044715f * x3));
    return 0.5f * x * (1.0f + t);
}

// ---------------- init / pack ----------------
__global__ void k_copy(const float* __restrict__ src, float* __restrict__ dst, int n) {
    int i = blockIdx.x * blockDim.x + threadIdx.x;
    if (i < n) dst[i] = src[i];
}

__global__ void k_pack(const float* __restrict__ Wq, const float* __restrict__ Wk,
                       const float* __restrict__ Wv) {
    int i = blockIdx.x * blockDim.x + threadIdx.x;
    if (i >= L_ * D_ * D3_) return;
    int c  = i % D3_;
    int ld = i / D3_;                 // l*D_ + d_in
    const float* src = (c < D_) ? Wq : (c < 2 * D_) ? Wk : Wv;
    int cc = c & (D_ - 1);
    g_wqkv[i] = src[(size_t)ld * D_ + cc];
}

// ---------------- neighbor selection (one warp per token) ----------------
__global__ __launch_bounds__(256) void k_neighbors(const float* __restrict__ ca,
                                                   const int* __restrict__ rnd) {
    int row  = blockIdx.x * 8 + (threadIdx.x >> 5);
    int lane = threadIdx.x & 31;
    if (row >= BN_) return;
    int b = row / N_, n = row - b * N_;
    const float* cb = ca + (size_t)b * N_ * 3;
    float x0 = cb[n*3+0], y0 = cb[n*3+1], z0 = cb[n*3+2];

    float d[24];
    #pragma unroll
    for (int t = 0; t < 24; t++) {
        int j = lane + 32 * t;
        float dx = x0 - cb[j*3+0];
        float dy = y0 - cb[j*3+1];
        float dz = z0 - cb[j*3+2];
        float dd = dx*dx + dy*dy + dz*dz;
        if (j == n) dd = 1e9f;        // self-exclusion (diag + big)
        d[t] = dd;
    }

    int sp[NSP];
    for (int r = 0; r < NSP; r++) {
        float bd = 1e30f; int bj = 0x7fffffff;
        #pragma unroll
        for (int t = 0; t < 24; t++) {
            int j = lane + 32 * t;
            if (d[t] < bd) { bd = d[t]; bj = j; }
        }
        #pragma unroll
        for (int o = 16; o; o >>= 1) {
            float od = __shfl_xor_sync(~0u, bd, o);
            int   oj = __shfl_xor_sync(~0u, bj, o);
            if (od < bd || (od == bd && oj < bj)) { bd = od; bj = oj; }
        }
        sp[r] = bj;                    // identical in all lanes (butterfly)
        if ((bj & 31) == lane) d[bj >> 5] = 1e30f;
    }

    // FIX (R6): K_=40 > warpSize. Each lane covers slots {lane, lane+32};
    // previously slots 32..39 (random neighbors 8..15) were never written.
    for (int s = lane; s < K_; s += 32) {
        int idx, val;
        if (s < 2 * NSEQ) {
            int off  = (s < NSEQ) ? (s - NSEQ) : (s - NSEQ + 1);
            int base = n + off;
            val = (base >= 0 && base < N_) ? 1 : 0;
            idx = min(max(base, 0), N_ - 1);
        } else if (s < 2 * NSEQ + NSP) {
            idx = sp[s - 2 * NSEQ];
            val = 1;
        } else {
            idx = rnd[(size_t)row * NRD + (s - 2 * NSEQ - NSP)];
            val = 1;
        }
        g_nidx[(size_t)row * K_ + s] = idx;
        g_nval[(size_t)row * K_ + s] = val;
    }
}

// ---------------- pair bias for ALL layers (one block per token) ----------------
__global__ __launch_bounds__(256) void k_bias(const float* __restrict__ pair,
                                              const float* __restrict__ Wb) {
    int row = blockIdx.x;
    int b = row / N_, n = row - b * N_;
    int tid = threadIdx.x;
    __shared__ float s_p[K_][P_ + 1];     // gathered pair rows
    __shared__ float s_w[L_ * P_ * H_];   // all Wb

    for (int i = tid; i < L_ * P_ * H_; i += 256) s_w[i] = Wb[i];
    for (int i = tid; i < K_ * P_; i += 256) {
        int k = i >> 6, p = i & 63;
        int j = g_nidx[(size_t)row * K_ + k];
        s_p[k][p] = pair[(((size_t)b * N_ + n) * N_ + j) * P_ + p];
    }
    __syncthreads();

    for (int u = tid; u < K_ * H_; u += 256) {
        int k = u >> 3, h = u & 7;
        float acc[L_] = {0.f,0.f,0.f,0.f,0.f,0.f};
        for (int p = 0; p < P_; p++) {
            float pv = s_p[k][p];
            #pragma unroll
            for (int l = 0; l < L_; l++) acc[l] += pv * s_w[(l * P_ + p) * H_ + h];
        }
        #pragma unroll
        for (int l = 0; l < L_; l++)
            g_bias[((size_t)l * BN_ + row) * (H_ * K_) + h * K_ + k] = acc[l];
    }
}

// ---------------- tiled SGEMM: C = A[MxK] * B[KxN]  (all dims % tile == 0) ----
// EPI: 0 = store, 1 = C += AB (residual), 2 = gelu(AB)
template<int EPI>
__global__ __launch_bounds__(256) void sgemm_k(const float* __restrict__ A,
                                               const float* __restrict__ B,
                                               float* __restrict__ C,
                                               int M, int N, int K) {
    __shared__ float As[16][68];
    __shared__ float Bs[16][68];
    const int tid = threadIdx.x;
    const int bm = blockIdx.y * 64;
    const int bn = blockIdx.x * 64;
    const int tx = tid & 15, ty = tid >> 4;
    const int ar = tid >> 2, ac = (tid & 3) << 2;
    const int br = tid >> 4, bc = (tid & 15) << 2;
    float acc[4][4] = {};

    for (int k0 = 0; k0 < K; k0 += 16) {
        float4 av = *(const float4*)(A + (size_t)(bm + ar) * K + k0 + ac);
        float4 bv = *(const float4*)(B + (size_t)(k0 + br) * N + bn + bc);
        As[ac+0][ar] = av.x; As[ac+1][ar] = av.y; As[ac+2][ar] = av.z; As[ac+3][ar] = av.w;
        *(float4*)&Bs[br][bc] = bv;
        __syncthreads();
        #pragma unroll
        for (int kk = 0; kk < 16; kk++) {
            float4 a = *(const float4*)&As[kk][ty << 2];
            float4 bq = *(const float4*)&Bs[kk][tx << 2];
            acc[0][0] += a.x*bq.x; acc[0][1] += a.x*bq.y; acc[0][2] += a.x*bq.z; acc[0][3] += a.x*bq.w;
            acc[1][0] += a.y*bq.x; acc[1][1] += a.y*bq.y; acc[1][2] += a.y*bq.z; acc[1][3] += a.y*bq.w;
            acc[2][0] += a.z*bq.x; acc[2][1] += a.z*bq.y; acc[2][2] += a.z*bq.z; acc[2][3] += a.z*bq.w;
            acc[3][0] += a.w*bq.x; acc[3][1] += a.w*bq.y; acc[3][2] += a.w*bq.z; acc[3][3] += a.w*bq.w;
        }
        __syncthreads();
    }
    #pragma unroll
    for (int i = 0; i < 4; i++) {
        float4 v = make_float4(acc[i][0], acc[i][1], acc[i][2], acc[i][3]);
        float4* cp = (float4*)(C + (size_t)(bm + (ty << 2) + i) * N + bn + (tx << 2));
        if (EPI == 1) { float4 o = *cp; v.x += o.x; v.y += o.y; v.z += o.z; v.w += o.w; }
        if (EPI == 2) { v.x = gelu_f(v.x); v.y = gelu_f(v.y); v.z = gelu_f(v.z); v.w = gelu_f(v.w); }
        *cp = v;
    }
}

// ---------------- row LayerNorm (optionally with adaLN modulation) ----------------
__global__ __launch_bounds__(256) void k_ln(const float* __restrict__ x,
                                            const float* __restrict__ condl,
                                            float* __restrict__ out) {
    int row = blockIdx.x, tid = threadIdx.x;
    const float* xr = x + (size_t)row * D_;
    float v0 = xr[tid], v1 = xr[tid + 256];
    float s = v0 + v1, ss = v0*v0 + v1*v1;
    #pragma unroll
    for (int o = 16; o; o >>= 1) {
        s  += __shfl_xor_sync(~0u, s,  o);
        ss += __shfl_xor_sync(~0u, ss, o);
    }
    __shared__ float sh[2][8];
    int w = tid >> 5;
    if ((tid & 31) == 0) { sh[0][w] = s; sh[1][w] = ss; }
    __syncthreads();
    s = 0.f; ss = 0.f;
    #pragma unroll
    for (int i = 0; i < 8; i++) { s += sh[0][i]; ss += sh[1][i]; }
    float m   = s * (1.f / 512.f);
    float var = ss * (1.f / 512.f) - m * m;
    float r   = rsqrtf(var + 1e-5f);
    float a0 = (v0 - m) * r, a1 = (v1 - m) * r;
    if (condl) {
        const float* cr = condl + (size_t)row * (2 * D_);
        a0 = a0 * (1.f + cr[tid])       + cr[D_ + tid];
        a1 = a1 * (1.f + cr[tid + 256]) + cr[D_ + tid + 256];
    }
    out[(size_t)row * D_ + tid]       = a0;
    out[(size_t)row * D_ + tid + 256] = a1;
}

// ---------------- per-head LN of q (cols 0..511) and k (cols 512..1023) -------
__global__ __launch_bounds__(512) void k_ln_heads(float* __restrict__ qkv) {
    int row = blockIdx.x, tid = threadIdx.x;
    int w = tid >> 5, lane = tid & 31;
    int base = (w < 8) ? (w * DH_) : (D_ + (w - 8) * DH_);
    float* p = qkv + (size_t)row * D3_ + base;
    float a = p[lane], c = p[lane + 32];
    float s = a + c, ss = a*a + c*c;
    #pragma unroll
    for (int o = 16; o; o >>= 1) {
        s  += __shfl_xor_sync(~0u, s,  o);
        ss += __shfl_xor_sync(~0u, ss, o);
    }
    float m   = s * (1.f / 64.f);
    float var = ss * (1.f / 64.f) - m * m;
    float r   = rsqrtf(var + 1e-5f);
    p[lane]      = (a - m) * r;
    p[lane + 32] = (c - m) * r;
}

// ---------------- sparse neighbor attention (one block per token, warp=head) ---
__global__ __launch_bounds__(256) void k_attn(int l) {
    int row = blockIdx.x;
    int b = row / N_;
    int tid = threadIdx.x;
    int h = tid >> 5, lane = tid & 31;

    __shared__ int   s_idx[K_];
    __shared__ int   s_val[K_];
    __shared__ float s_b [H_][K_];
    __shared__ float s_sc[H_][K_];

    for (int s = tid; s < K_; s += 256) {
        s_idx[s] = g_nidx[(size_t)row * K_ + s];
        s_val[s] = g_nval[(size_t)row * K_ + s];
    }
    const float* bias = g_bias + ((size_t)l * BN_ + row) * (H_ * K_);
    for (int i = tid; i < H_ * K_; i += 256) ((float*)s_b)[i] = bias[i];
    __syncthreads();

    const float* q = g_qkv + (size_t)row * D3_ + h * DH_;
    float q0 = q[lane], q1 = q[lane + 32];
    const float* kbase = g_qkv + (size_t)b * N_ * D3_ + D_     + h * DH_;
    const float* vbase = g_qkv + (size_t)b * N_ * D3_ + 2 * D_ + h * DH_;

    for (int k = 0; k < K_; k++) {
        int j = s_idx[k];
        const float* kr = kbase + (size_t)j * D3_;
        float p = q0 * kr[lane] + q1 * kr[lane + 32];
        #pragma unroll
        for (int o = 16; o; o >>= 1) p += __shfl_xor_sync(~0u, p, o);
        if (lane == 0)
            s_sc[h][k] = s_val[k] ? (p * 0.125f + s_b[h][k]) : -1e9f;
    }
    __syncwarp();

    float v0 = s_sc[h][lane];
    float v1 = (lane < K_ - 32) ? s_sc[h][lane + 32] : -1e30f;
    float mx = fmaxf(v0, v1);
    #pragma unroll
    for (int o = 16; o; o >>= 1) mx = fmaxf(mx, __shfl_xor_sync(~0u, mx, o));
    float e0 = expf(v0 - mx);
    float e1 = (lane < K_ - 32) ? expf(v1 - mx) : 0.f;
    float sum = e0 + e1;
    #pragma unroll
    for (int o = 16; o; o >>= 1) sum += __shfl_xor_sync(~0u, sum, o);
    float inv = 1.f / sum;
    s_sc[h][lane] = e0 * inv;
    if (lane < K_ - 32) s_sc[h][lane + 32] = e1 * inv;
    __syncwarp();

    float o0 = 0.f, o1 = 0.f;
    for (int k = 0; k < K_; k++) {
        int j = s_idx[k];
        float a = s_sc[h][k];
        const float* vr = vbase + (size_t)j * D3_;
        o0 += a * vr[lane];
        o1 += a * vr[lane + 32];
    }
    g_o[(size_t)row * D_ + h * DH_ + lane]      = o0;
    g_o[(size_t)row * D_ + h * DH_ + lane + 32] = o1;
}

// ---------------- final projection: out = [hN@W_ca | hN@W_lat]  (11 cols) -----
__global__ __launch_bounds__(352) void k_final(const float* __restrict__ xn,
                                               const float* __restrict__ Wca,
                                               const float* __restrict__ Wlat,
                                               float* __restrict__ out) {
    int row = blockIdx.x;
    int o = threadIdx.x >> 5, lane = threadIdx.x & 31;
    const float* xr = xn + (size_t)row * D_;
    const float* w; int stride, col;
    if (o < 3) { w = Wca;  stride = 3; col = o; }
    else       { w = Wlat; stride = 8; col = o - 3; }
    float s = 0.f;
    for (int d = lane; d < D_; d += 32) s += xr[d] * w[d * stride + col];
    #pragma unroll
    for (int x = 16; x; x >>= 1) s += __shfl_xor_sync(~0u, s, x);
    if (lane == 0) out[(size_t)row * 11 + o] = s;
}

// ---------------- host orchestration ----------------
extern "C" void kernel_launch(void* const* d_in, const int* in_sizes, int n_in,
                              void* d_out, int out_size) {
    const float* seqs = (const float*)d_in[0];
    const float* cond = (const float*)d_in[1];
    const float* ca   = (const float*)d_in[2];
    const float* pair = (const float*)d_in[3];
    const int*   rnd  = (const int*)  d_in[5];
    const float* Wq   = (const float*)d_in[6];
    const float* Wk   = (const float*)d_in[7];
    const float* Wv   = (const float*)d_in[8];
    const float* Wo   = (const float*)d_in[9];
    const float* Wb   = (const float*)d_in[10];
    const float* Wc   = (const float*)d_in[11];
    const float* W1   = (const float*)d_in[12];
    const float* W2   = (const float*)d_in[13];
    const float* Wca  = (const float*)d_in[14];
    const float* Wlat = (const float*)d_in[15];
    float* out = (float*)d_out;

    void* p;
    cudaGetSymbolAddress(&p, g_x);    float* px    = (float*)p;
    cudaGetSymbolAddress(&p, g_h);    float* ph    = (float*)p;
    cudaGetSymbolAddress(&p, g_xn);   float* pxn   = (float*)p;
    cudaGetSymbolAddress(&p, g_qkv);  float* pqkv  = (float*)p;
    cudaGetSymbolAddress(&p, g_o);    float* po    = (float*)p;
    cudaGetSymbolAddress(&p, g_t1);   float* pt1   = (float*)p;
    cudaGetSymbolAddress(&p, g_cond); float* pcond = (float*)p;
    cudaGetSymbolAddress(&p, g_wqkv); float* pwqkv = (float*)p;

    // prologue (layer-invariant)
    k_copy<<<(BN_ * D_ + 1023) / 1024, 1024>>>(seqs, px, BN_ * D_);
    k_pack<<<(L_ * D_ * D3_ + 255) / 256, 256>>>(Wq, Wk, Wv);
    k_neighbors<<<BN_ / 8, 256>>>(ca, rnd);
    k_bias<<<BN_, 256>>>(pair, Wb);
    for (int l = 0; l < L_; l++)
        sgemm_k<0><<<dim3((2 * D_) / 64, BN_ / 64), 256>>>(
            cond, Wc + (size_t)l * C_ * 2 * D_,
            pcond + (size_t)l * BN_ * 2 * D_, BN_, 2 * D_, C_);

    // transformer layers
    for (int l = 0; l < L_; l++) {
        k_ln<<<BN_, 256>>>(px, pcond + (size_t)l * BN_ * 2 * D_, ph);
        sgemm_k<0><<<dim3(D3_ / 64, BN_ / 64), 256>>>(
            ph, pwqkv + (size_t)l * D_ * D3_, pqkv, BN_, D3_, D_);
        k_ln_heads<<<BN_, 512>>>(pqkv);
        k_attn<<<BN_, 256>>>(l);
        sgemm_k<1><<<dim3(D_ / 64, BN_ / 64), 256>>>(
            po, Wo + (size_t)l * D_ * D_, px, BN_, D_, D_);
        k_ln<<<BN_, 256>>>(px, nullptr, pxn);
        sgemm_k<2><<<dim3(D4_ / 64, BN_ / 64), 256>>>(
            pxn, W1 + (size_t)l * D_ * D4_, pt1, BN_, D4_, D_);
        sgemm_k<1><<<dim3(D_ / 64, BN_ / 64), 256>>>(
            pt1, W2 + (size_t)l * D4_ * D_, px, BN_, D_, D4_);
    }

    // epilogue
    k_ln<<<BN_, 256>>>(px, nullptr, pxn);
    k_final<<<BN_, 352>>>(pxn, Wca, Wlat, out);
}